// round 14
// baseline (speedup 1.0000x reference)
#include <cuda_runtime.h>
#include <stdint.h>

// X (B=4, L=8192, D=32, N=32) fp32, cumsum along L (axis=1).
// Inner = D*N = 1024 contiguous floats per (b,l).
#define BB      4
#define LL      8192
#define INNER   1024
#define SEGW    256                    // lanes per CTA (segment width)
#define NSEG    (INNER / SEGW)         // 4 segments
#define CHUNK   16                     // L rows per tile (16 regs for v[])
#define NT      (LL / CHUNK)           // 512 L-tiles per chain
#define NCHAIN  (BB * NSEG)            // 16 independent (b,seg) chains
#define NTILES  (NCHAIN * NT)          // 8192 tiles per launch
#define OCC     6                      // CTAs per SM
#define GRID    (OCC * 148)            // 888 persistent CTAs, all co-resident
#define TPL     (NTILES + GRID)        // tickets consumed per launch (exact)
#define LOOKW   4                      // lookback window (independent loads)

// Decoupled-lookback state: packed {flag:32 | value_bits:32} per (tile, lane).
// Flag+value travel in ONE 8-byte relaxed access => no fences needed anywhere.
//   flag <  fbase   : stale (earlier launch)
//   flag == fbase   : aggregate available
//   flag == fbase+1 : inclusive prefix available
// fbase = 2*(ticket/TPL) + 2; g_ticket is monotonic forever (no init kernel).
__device__ unsigned long long g_state[(size_t)NTILES * SEGW];   // 16 MiB
__device__ unsigned int g_ticket = 0;

__device__ __forceinline__ unsigned long long ld_relaxed_u64(const unsigned long long* p) {
    unsigned long long v;
    asm volatile("ld.relaxed.gpu.global.b64 %0, [%1];" : "=l"(v) : "l"(p));
    return v;
}
__device__ __forceinline__ void st_relaxed_u64(unsigned long long* p, unsigned long long v) {
    asm volatile("st.relaxed.gpu.global.b64 [%0], %1;" :: "l"(p), "l"(v));
}
__device__ __forceinline__ unsigned long long pack_fv(unsigned int flag, float val) {
    return ((unsigned long long)flag << 32) | (unsigned long long)__float_as_uint(val);
}
__device__ __forceinline__ void cp_async16(uint32_t smem_addr, const void* gmem) {
    asm volatile("cp.async.cg.shared.global [%0], [%1], 16;"
                 :: "r"(smem_addr), "l"(gmem));
}
__device__ __forceinline__ void cp_async_commit() {
    asm volatile("cp.async.commit_group;");
}
__device__ __forceinline__ void cp_async_wait0() {
    asm volatile("cp.async.wait_group 0;");
}

// Element index of row 0, lane 0 of a tile.
__device__ __forceinline__ size_t tile_row0(int tloc) {
    const int chain = tloc & (NCHAIN - 1);
    const int ltile = tloc >> 4;               // NCHAIN = 16
    const int b     = chain >> 2;              // NSEG = 4
    const int seg   = chain & 3;
    return ((size_t)b * LL + (size_t)ltile * CHUNK) * INNER + (size_t)seg * SEGW;
}

__global__ __launch_bounds__(SEGW, OCC)
void scan_kernel(const float* __restrict__ X, float* __restrict__ Y) {
    __shared__ float s_buf[CHUNK * SEGW];      // 16 KB staging
    __shared__ unsigned int s_t;

    const int tid  = (int)threadIdx.x;
    const int lane = tid;

    uint32_t s_base;
    asm("{ .reg .u64 t; cvta.to.shared.u64 t, %1; cvt.u32.u64 %0, t; }"
        : "=r"(s_base) : "l"(s_buf));

    if (tid == 0) s_t = atomicAdd(&g_ticket, 1u);
    __syncthreads();

    const unsigned int t0    = s_t;
    const unsigned int epoch = t0 / TPL;                 // launch-unique
    const unsigned int lb    = epoch * TPL;              // launch ticket base
    const unsigned int fbase = epoch * 2u + 2u;          // agg flag; incl = +1
    int tloc = (int)(t0 - lb);
    if (tloc >= NTILES) return;                          // terminating ticket

    // cp.async sweep geometry: 4 sweeps of 4 KB; thread covers 16 B per sweep.
    const int sub  = tid >> 6;                 // row-within-4 group
    const int colb = (tid & 63) * 16;          // byte column within row
    const uint32_t s_dst0 = s_base + (uint32_t)(sub * 1024 + colb);

    // Prologue: prefetch first tile.
    {
        const char* src = (const char*)(X + tile_row0(tloc));
#pragma unroll
        for (int s = 0; s < CHUNK / 4; ++s)
            cp_async16(s_dst0 + (uint32_t)s * 4096u,
                       src + (size_t)(s * 4 + sub) * (INNER * 4) + colb);
        cp_async_commit();
    }

    for (;;) {
        cp_async_wait0();
        __syncthreads();                       // staged tile visible to all

        // ---- load from smem + local inclusive scan ----
        float v[CHUNK];
#pragma unroll
        for (int i = 0; i < CHUNK; ++i) v[i] = s_buf[i * SEGW + lane];
#pragma unroll
        for (int i = 1; i < CHUNK; ++i) v[i] += v[i - 1];
        const float total = v[CHUNK - 1];

        const int chain = tloc & (NCHAIN - 1);
        const int ltile = tloc >> 4;
        const size_t chain_base = ((size_t)chain * NT) * SEGW + lane;
        unsigned long long* my_state = &g_state[chain_base + (size_t)ltile * SEGW];

        // Publish aggregate (inclusive for ltile 0) — fence-free packed word.
        st_relaxed_u64(my_state,
                       pack_fv(ltile == 0 ? fbase + 1u : fbase, total));

        // Next ticket. (WAR on s_t safe: last read before the top barrier.)
        if (tid == 0) s_t = atomicAdd(&g_ticket, 1u);
        __syncthreads();                       // LDS drained + s_t visible
        const int tloc1 = (int)(s_t - lb);

        // Prefetch next tile into the reusable buffer; overlaps lookback.
        if (tloc1 < NTILES) {
            const char* src = (const char*)(X + tile_row0(tloc1));
#pragma unroll
            for (int s = 0; s < CHUNK / 4; ++s)
                cp_async16(s_dst0 + (uint32_t)s * 4096u,
                           src + (size_t)(s * 4 + sub) * (INNER * 4) + colb);
            cp_async_commit();
        }

        // ---- decoupled lookback (LOOKW independent loads per round) ----
        float excl = 0.0f;
        if (ltile != 0) {
            const unsigned long long* st_row = &g_state[chain_base];
            int pt = ltile - 1;
            for (;;) {
                unsigned long long w[LOOKW];
                const int n = (pt + 1 < LOOKW) ? (pt + 1) : LOOKW;
#pragma unroll
                for (int j = 0; j < LOOKW; ++j)
                    if (j < n) w[j] = ld_relaxed_u64(st_row + (size_t)(pt - j) * SEGW);

                int consumed = 0;
                bool done = false;
#pragma unroll
                for (int j = 0; j < LOOKW; ++j) {
                    if (j >= n || done) continue;
                    unsigned int f = (unsigned int)(w[j] >> 32);
                    if (f < fbase) break;                      // stale: stop
                    excl += __uint_as_float((unsigned int)w[j]);
                    ++consumed;
                    if (f == fbase + 1u) done = true;          // found inclusive
                }
                pt -= consumed;
                if (done) break;
                if (consumed == 0) __nanosleep(32);
            }
            st_relaxed_u64(my_state, pack_fv(fbase + 1u, excl + total));
        }

        // ---- store outputs (coalesced) ----
        {
            float* q = Y + tile_row0(tloc) + lane;
#pragma unroll
            for (int i = 0; i < CHUNK; ++i) q[(size_t)i * INNER] = v[i] + excl;
        }

        if (tloc1 >= NTILES) break;
        tloc = tloc1;
    }
}

extern "C" void kernel_launch(void* const* d_in, const int* in_sizes, int n_in,
                              void* d_out, int out_size) {
    const float* X = (const float*)d_in[0];
    float*       Y = (float*)d_out;
    (void)in_sizes; (void)n_in; (void)out_size;

    scan_kernel<<<GRID, SEGW>>>(X, Y);
}

// round 15
// speedup vs baseline: 1.0726x; 1.0726x over previous
#include <cuda_runtime.h>
#include <stdint.h>

// X (B=4, L=8192, D=32, N=32) fp32, cumsum along L (axis=1).
// Inner = D*N = 1024 contiguous floats per (b,l).
#define BB      4
#define LL      8192
#define INNER   1024
#define SEGW    256                    // lanes per CTA (segment width)
#define NSEG    (INNER / SEGW)         // 4 segments
#define CHUNK   32                     // L rows per tile
#define NT      (LL / CHUNK)           // 256 L-tiles per chain
#define NCHAIN  (BB * NSEG)            // 16 independent (b,seg) chains
#define NTILES  (NCHAIN * NT)          // 4096 tiles per launch
#define GRID    592                    // persistent CTAs (4/SM x 148 SMs)
#define TPL     (NTILES + GRID)        // tickets consumed per launch (exact)

// Decoupled-lookback state: packed {flag:32 | value_bits:32} per (tile, lane).
// Flag+value travel in ONE 8-byte relaxed access => no fences needed anywhere.
//   flag <  fbase   : stale (earlier launch)
//   flag == fbase   : aggregate available
//   flag == fbase+1 : inclusive prefix available
// fbase = 2*(ticket/TPL) + 2; g_ticket is monotonic forever (no init kernel).
__device__ unsigned long long g_state[(size_t)NTILES * SEGW];   // 8 MiB
__device__ unsigned int g_ticket = 0;

__device__ __forceinline__ unsigned long long ld_relaxed_u64(const unsigned long long* p) {
    unsigned long long v;
    asm volatile("ld.relaxed.gpu.global.b64 %0, [%1];" : "=l"(v) : "l"(p));
    return v;
}
__device__ __forceinline__ void st_relaxed_u64(unsigned long long* p, unsigned long long v) {
    asm volatile("st.relaxed.gpu.global.b64 [%0], %1;" :: "l"(p), "l"(v));
}
__device__ __forceinline__ unsigned long long pack_fv(unsigned int flag, float val) {
    return ((unsigned long long)flag << 32) | (unsigned long long)__float_as_uint(val);
}
__device__ __forceinline__ void cp_async16(uint32_t smem_addr, const void* gmem) {
    asm volatile("cp.async.cg.shared.global [%0], [%1], 16;"
                 :: "r"(smem_addr), "l"(gmem));
}
__device__ __forceinline__ void cp_async_commit() {
    asm volatile("cp.async.commit_group;");
}
__device__ __forceinline__ void cp_async_wait0() {
    asm volatile("cp.async.wait_group 0;");
}

// Element index of row 0, lane 0 of a tile.
__device__ __forceinline__ size_t tile_row0(int tloc) {
    const int chain = tloc & (NCHAIN - 1);
    const int ltile = tloc >> 4;               // NCHAIN = 16
    const int b     = chain >> 2;              // NSEG = 4
    const int seg   = chain & 3;
    return ((size_t)b * LL + (size_t)ltile * CHUNK) * INNER + (size_t)seg * SEGW;
}

__global__ __launch_bounds__(SEGW, 4)
void scan_kernel(const float* __restrict__ X, float* __restrict__ Y) {
    __shared__ float s_buf[CHUNK * SEGW];      // 32 KB staging
    __shared__ unsigned int s_t;

    const int tid  = (int)threadIdx.x;
    const int lane = tid;
    const int lid  = tid & 31;

    uint32_t s_base;
    asm("{ .reg .u64 t; cvta.to.shared.u64 t, %1; cvt.u32.u64 %0, t; }"
        : "=r"(s_base) : "l"(s_buf));

    if (tid == 0) s_t = atomicAdd(&g_ticket, 1u);
    __syncthreads();

    const unsigned int t0    = s_t;
    const unsigned int epoch = t0 / TPL;                 // launch-unique
    const unsigned int lb    = epoch * TPL;              // launch ticket base
    const unsigned int fbase = epoch * 2u + 2u;          // agg flag; incl = +1
    int tloc = (int)(t0 - lb);
    if (tloc >= NTILES) return;                          // terminating ticket

    // cp.async sweep geometry: 8 sweeps of 4 KB; thread covers 16 B per sweep.
    const int sub  = tid >> 6;                 // row-within-4 group
    const int colb = (tid & 63) * 16;          // byte column within row
    const uint32_t s_dst0 = s_base + (uint32_t)(sub * 1024 + colb);

    // Prologue: prefetch first tile.
    {
        const char* src = (const char*)(X + tile_row0(tloc));
#pragma unroll
        for (int s = 0; s < CHUNK / 4; ++s)
            cp_async16(s_dst0 + (uint32_t)s * 4096u,
                       src + (size_t)(s * 4 + sub) * (INNER * 4) + colb);
        cp_async_commit();
    }

    for (;;) {
        cp_async_wait0();
        __syncthreads();                       // staged tile visible to all

        // ---- load from smem + local inclusive scan ----
        float v[CHUNK];
#pragma unroll
        for (int i = 0; i < CHUNK; ++i) v[i] = s_buf[i * SEGW + lane];
#pragma unroll
        for (int i = 1; i < CHUNK; ++i) v[i] += v[i - 1];
        const float total = v[CHUNK - 1];

        const int chain = tloc & (NCHAIN - 1);
        const int ltile = tloc >> 4;
        const size_t chain_base = ((size_t)chain * NT) * SEGW + lane;
        const unsigned long long* st_row = &g_state[chain_base];
        unsigned long long* my_state = &g_state[chain_base + (size_t)ltile * SEGW];

        // Publish aggregate (inclusive for ltile 0) — fence-free packed word.
        st_relaxed_u64(my_state,
                       pack_fv(ltile == 0 ? fbase + 1u : fbase, total));

        // ---- pre-issue probe round 1 (its latency hides under barrier+cp.async) ----
        int base = 0;
        unsigned long long wp = 0ull;
        if (ltile != 0) {
            base = (ltile > 44) ? (ltile - 13) : (ltile - 1);
            const int idx = base - lid;
            if (idx >= 0)
                wp = ld_relaxed_u64(st_row + (size_t)idx * SEGW);
        }

        // Next ticket. (WAR on s_t safe: last read before the top barrier.)
        if (tid == 0) s_t = atomicAdd(&g_ticket, 1u);
        __syncthreads();                       // LDS drained + s_t visible
        const int tloc1 = (int)(s_t - lb);

        // Prefetch next tile into the reusable buffer; overlaps lookback.
        if (tloc1 < NTILES) {
            const char* src = (const char*)(X + tile_row0(tloc1));
#pragma unroll
            for (int s = 0; s < CHUNK / 4; ++s)
                cp_async16(s_dst0 + (uint32_t)s * 4096u,
                           src + (size_t)(s * 4 + sub) * (INNER * 4) + colb);
            cp_async_commit();
        }

        // ---- lookback: probe for newest inclusive, then stream-gather up ----
        float excl = 0.0f;
        if (ltile != 0) {
            // Probe: warp-parallel flag test over a 32-tile window.
            int m;
            for (;;) {
                const int idx = base - lid;
                const bool incl = (idx >= 0) &&
                    ((unsigned int)(wp >> 32) == fbase + 1u);
                const unsigned int bi = __ballot_sync(0xffffffffu, incl);
                if (bi) { m = base - (__ffs(bi) - 1); break; }   // newest incl
                const int nb = (base >= 32) ? (base - 32) : base;
                if (nb == base) __nanosleep(64);  // bottom window: wait for t0
                base = nb;
                const int idx2 = base - lid;
                wp = (idx2 >= 0) ? ld_relaxed_u64(st_row + (size_t)idx2 * SEGW)
                                 : 0ull;
            }

            // Anchor: THIS lane's word at m must be inclusive (probe used a
            // per-lane proxy; publisher lanes may race by a few cycles).
            unsigned long long w = ld_relaxed_u64(st_row + (size_t)m * SEGW);
            while ((unsigned int)(w >> 32) != fbase + 1u) {
                __nanosleep(20);
                w = ld_relaxed_u64(st_row + (size_t)m * SEGW);
            }
            excl = __uint_as_float((unsigned int)w);

            // Stream m+1..ltile-1: fixed addresses, double-buffered batch of 3
            // (next batch issues before current consumes => ~1 exposed round).
            auto consume = [&](unsigned long long u, int kk) {
                unsigned int f = (unsigned int)(u >> 32);
                while (f < fbase) {                 // rare: publisher lane race
                    __nanosleep(20);
                    u = ld_relaxed_u64(st_row + (size_t)kk * SEGW);
                    f = (unsigned int)(u >> 32);
                }
                const float val = __uint_as_float((unsigned int)u);
                excl = (f == fbase + 1u) ? val : (excl + val);  // incl => reset
            };

            int k  = m + 1;
            int nA = ltile - k; nA = (nA > 3) ? 3 : nA;
            unsigned long long A0 = 0, A1 = 0, A2 = 0;
            if (nA > 0) A0 = ld_relaxed_u64(st_row + (size_t)(k + 0) * SEGW);
            if (nA > 1) A1 = ld_relaxed_u64(st_row + (size_t)(k + 1) * SEGW);
            if (nA > 2) A2 = ld_relaxed_u64(st_row + (size_t)(k + 2) * SEGW);
            while (nA > 0) {
                const int kB = k + nA;
                int nB = ltile - kB; nB = (nB < 0) ? 0 : ((nB > 3) ? 3 : nB);
                unsigned long long B0 = 0, B1 = 0, B2 = 0;
                if (nB > 0) B0 = ld_relaxed_u64(st_row + (size_t)(kB + 0) * SEGW);
                if (nB > 1) B1 = ld_relaxed_u64(st_row + (size_t)(kB + 1) * SEGW);
                if (nB > 2) B2 = ld_relaxed_u64(st_row + (size_t)(kB + 2) * SEGW);
                consume(A0, k + 0);
                if (nA > 1) consume(A1, k + 1);
                if (nA > 2) consume(A2, k + 2);
                k = kB; nA = nB; A0 = B0; A1 = B1; A2 = B2;
            }

            st_relaxed_u64(my_state, pack_fv(fbase + 1u, excl + total));
        }

        // ---- store outputs (coalesced) ----
        {
            float* q = Y + tile_row0(tloc) + lane;
#pragma unroll
            for (int i = 0; i < CHUNK; ++i) q[(size_t)i * INNER] = v[i] + excl;
        }

        if (tloc1 >= NTILES) break;
        tloc = tloc1;
    }
}

extern "C" void kernel_launch(void* const* d_in, const int* in_sizes, int n_in,
                              void* d_out, int out_size) {
    const float* X = (const float*)d_in[0];
    float*       Y = (float*)d_out;
    (void)in_sizes; (void)n_in; (void)out_size;

    scan_kernel<<<GRID, SEGW>>>(X, Y);
}

// round 16
// speedup vs baseline: 1.1385x; 1.0615x over previous
#include <cuda_runtime.h>
#include <stdint.h>

// X (B=4, L=8192, D=32, N=32) fp32, cumsum along L (axis=1).
// Inner = D*N = 1024 contiguous floats per (b,l).
#define BB      4
#define LL      8192
#define INNER   1024
#define SEGW    256                    // lanes per CTA (segment width)
#define NSEG    (INNER / SEGW)         // 4 segments
#define CHUNK   32                     // L rows per tile
#define HALF    16                     // rows per half-tile pipeline unit
#define NT      (LL / CHUNK)           // 256 L-tiles per chain
#define NCHAIN  (BB * NSEG)            // 16 independent (b,seg) chains
#define NTILES  (NCHAIN * NT)          // 4096 tiles per launch
#define GRID    592                    // persistent CTAs (4/SM x 148 SMs)
#define TPL     (NTILES + GRID)        // tickets consumed per launch (exact)
#define LOOKW   6                      // lookback window (independent loads)
#define HALF_BYTES (HALF * SEGW * 4)   // 16 KB per half

// Decoupled-lookback state: packed {flag:32 | value_bits:32} per (tile, lane).
// Flag+value travel in ONE 8-byte relaxed access => no fences needed anywhere.
//   flag <  fbase   : stale (earlier launch)
//   flag == fbase   : aggregate available
//   flag == fbase+1 : inclusive prefix available
// fbase = 2*(ticket/TPL) + 2; g_ticket is monotonic forever (no init kernel).
__device__ unsigned long long g_state[(size_t)NTILES * SEGW];   // 8 MiB
__device__ unsigned int g_ticket = 0;

__device__ __forceinline__ unsigned long long ld_relaxed_u64(const unsigned long long* p) {
    unsigned long long v;
    asm volatile("ld.relaxed.gpu.global.b64 %0, [%1];" : "=l"(v) : "l"(p));
    return v;
}
__device__ __forceinline__ void st_relaxed_u64(unsigned long long* p, unsigned long long v) {
    asm volatile("st.relaxed.gpu.global.b64 [%0], %1;" :: "l"(p), "l"(v));
}
__device__ __forceinline__ unsigned long long pack_fv(unsigned int flag, float val) {
    return ((unsigned long long)flag << 32) | (unsigned long long)__float_as_uint(val);
}
__device__ __forceinline__ void cp_async16(uint32_t smem_addr, const void* gmem) {
    asm volatile("cp.async.cg.shared.global [%0], [%1], 16;"
                 :: "r"(smem_addr), "l"(gmem));
}
__device__ __forceinline__ void cp_async_commit() {
    asm volatile("cp.async.commit_group;");
}
__device__ __forceinline__ void cp_async_wait0() {
    asm volatile("cp.async.wait_group 0;");
}
__device__ __forceinline__ void cp_async_wait1() {
    asm volatile("cp.async.wait_group 1;");
}

// Element index of row 0, lane 0 of a tile.
__device__ __forceinline__ size_t tile_row0(int tloc) {
    const int chain = tloc & (NCHAIN - 1);
    const int ltile = tloc >> 4;               // NCHAIN = 16
    const int b     = chain >> 2;              // NSEG = 4
    const int seg   = chain & 3;
    return ((size_t)b * LL + (size_t)ltile * CHUNK) * INNER + (size_t)seg * SEGW;
}

__global__ __launch_bounds__(SEGW, 4)
void scan_kernel(const float* __restrict__ X, float* __restrict__ Y) {
    __shared__ float s_buf[CHUNK * SEGW];      // 32 KB = two 16 KB halves
    __shared__ unsigned int s_t;

    const int tid  = (int)threadIdx.x;
    const int lane = tid;

    uint32_t s_base;
    asm("{ .reg .u64 t; cvta.to.shared.u64 t, %1; cvt.u32.u64 %0, t; }"
        : "=r"(s_base) : "l"(s_buf));

    if (tid == 0) s_t = atomicAdd(&g_ticket, 1u);
    __syncthreads();

    const unsigned int t0    = s_t;
    const unsigned int epoch = t0 / TPL;                 // launch-unique
    const unsigned int lb    = epoch * TPL;              // launch ticket base
    const unsigned int fbase = epoch * 2u + 2u;          // agg flag; incl = +1
    int tloc = (int)(t0 - lb);
    if (tloc >= NTILES) return;                          // terminating ticket

    // cp.async sweep geometry: 4 sweeps of 4 KB per half; 16 B per thread/sweep.
    const int sub  = tid >> 6;                 // row-within-4 group
    const int colb = (tid & 63) * 16;          // byte column within row
    const uint32_t s_dst0 = s_base + (uint32_t)(sub * 1024 + colb);

    // Issue one half (hsel 0/1) of tile t as its own commit group.
    auto issue_half = [&](int t, int hsel) {
        const char* src = (const char*)(X + tile_row0(t))
                        + (size_t)(hsel * HALF) * (INNER * 4);
        const uint32_t dst = s_dst0 + (uint32_t)(hsel * HALF_BYTES);
#pragma unroll
        for (int s = 0; s < HALF / 4; ++s)
            cp_async16(dst + (uint32_t)s * 4096u,
                       src + (size_t)(s * 4 + sub) * (INNER * 4) + colb);
        cp_async_commit();
    };

    // Prologue: both halves of the first tile (groups alternate H0,H1,H0,...).
    issue_half(tloc, 0);
    issue_half(tloc, 1);

    for (;;) {
        // ---- H0 ready (H1 still streaming); scan first half ----
        cp_async_wait1();
        __syncthreads();
        float v[CHUNK];
#pragma unroll
        for (int i = 0; i < HALF; ++i) v[i] = s_buf[i * SEGW + lane];
#pragma unroll
        for (int i = 1; i < HALF; ++i) v[i] += v[i - 1];

        // Acquire next ticket; barrier doubles as "H0 LDS drained".
        if (tid == 0) s_t = atomicAdd(&g_ticket, 1u);
        __syncthreads();
        const int tloc1 = (int)(s_t - lb);
        const bool valid = (tloc1 < NTILES);

        // Refill H0 with next tile's first half (overlaps H1 wait + everything).
        if (valid) issue_half(tloc1, 0);

        // ---- H1 ready; finish scan ----
        if (valid) cp_async_wait1(); else cp_async_wait0();
        __syncthreads();
#pragma unroll
        for (int i = HALF; i < CHUNK; ++i) v[i] = s_buf[i * SEGW + lane];
#pragma unroll
        for (int i = HALF; i < CHUNK; ++i) v[i] += v[i - 1];
        const float total = v[CHUNK - 1];

        const int chain = tloc & (NCHAIN - 1);
        const int ltile = tloc >> 4;
        const size_t chain_base = ((size_t)chain * NT) * SEGW + lane;
        unsigned long long* my_state = &g_state[chain_base + (size_t)ltile * SEGW];

        // Publish aggregate (inclusive for ltile 0) — fence-free packed word.
        st_relaxed_u64(my_state,
                       pack_fv(ltile == 0 ? fbase + 1u : fbase, total));

        // H1 LDS drained -> refill H1 with next tile's second half.
        __syncthreads();
        if (valid) issue_half(tloc1, 1);

        // ---- decoupled lookback (LOOKW independent loads per round) ----
        float excl = 0.0f;
        if (ltile != 0) {
            const unsigned long long* st_row = &g_state[chain_base];
            int pt = ltile - 1;
            for (;;) {
                unsigned long long w[LOOKW];
                const int n = (pt + 1 < LOOKW) ? (pt + 1) : LOOKW;
#pragma unroll
                for (int j = 0; j < LOOKW; ++j)
                    if (j < n) w[j] = ld_relaxed_u64(st_row + (size_t)(pt - j) * SEGW);

                int consumed = 0;
                bool done = false;
#pragma unroll
                for (int j = 0; j < LOOKW; ++j) {
                    if (j >= n || done) continue;
                    unsigned int f = (unsigned int)(w[j] >> 32);
                    if (f < fbase) break;                      // stale: stop
                    excl += __uint_as_float((unsigned int)w[j]);
                    ++consumed;
                    if (f == fbase + 1u) done = true;          // found inclusive
                }
                pt -= consumed;
                if (done) break;
                if (consumed == 0) __nanosleep(32);
            }
            st_relaxed_u64(my_state, pack_fv(fbase + 1u, excl + total));
        }

        // ---- store outputs (coalesced) ----
        {
            float* q = Y + tile_row0(tloc) + lane;
#pragma unroll
            for (int i = 0; i < CHUNK; ++i) q[(size_t)i * INNER] = v[i] + excl;
        }

        if (!valid) break;
        tloc = tloc1;
    }
}

extern "C" void kernel_launch(void* const* d_in, const int* in_sizes, int n_in,
                              void* d_out, int out_size) {
    const float* X = (const float*)d_in[0];
    float*       Y = (float*)d_out;
    (void)in_sizes; (void)n_in; (void)out_size;

    scan_kernel<<<GRID, SEGW>>>(X, Y);
}